// round 1
// baseline (speedup 1.0000x reference)
#include <cuda_runtime.h>
#include <math.h>

// Problem constants: B=8, S=1024, D=1024, H=16, hd=64
#define NB 8
#define NS 1024
#define ND 1024
#define NH 16
#define HD 64

// Scratch (allocation-free rule: __device__ globals)
__device__ float g_Q[NB * NH * NS * HD];   // [B,H,S,hd]
__device__ float g_K[NB * NH * NS * HD];
__device__ float g_V[NB * NH * NS * HD];
__device__ float g_ctx[NB * NS * ND];      // [B,S,D]

// ---------------------------------------------------------------------------
// Generic fp32 tiled GEMM: C[M,N] = A[M,K] @ B[K,N] + bias
// BM=BN=128, BK=16, 256 threads, 8x8 register tile per thread.
// MODE 0: QK projection epilogue -> scatter to g_Q / g_K  (N=2048)
// MODE 1: V  projection epilogue -> scatter to g_V        (N=1024)
// MODE 2: plain epilogue, A taken from g_ctx, out = d_out (N=1024)
// M = 8192, K = 1024 in all cases (no bounds checks needed).
// ---------------------------------------------------------------------------
template <int MODE>
__global__ __launch_bounds__(256) void gemm_f32(
    const float* __restrict__ A, const float* __restrict__ Bw,
    const float* __restrict__ bias, float* __restrict__ out,
    int K, int N)
{
    __shared__ float As[16][132];   // [k][m], padded
    __shared__ float Bs[16][128];   // [k][n]

    const int tid = threadIdx.x;
    const int ty = tid >> 4;        // 0..15
    const int tx = tid & 15;        // 0..15
    const int m0 = blockIdx.y * 128;
    const int n0 = blockIdx.x * 128;

    const float* Ap = (MODE == 2) ? (const float*)g_ctx : A;

    float acc[8][8];
#pragma unroll
    for (int i = 0; i < 8; i++)
#pragma unroll
        for (int j = 0; j < 8; j++) acc[i][j] = 0.0f;

    for (int k0 = 0; k0 < K; k0 += 16) {
        // Load A tile [128 x 16] -> As transposed [16][128]
#pragma unroll
        for (int l = 0; l < 2; l++) {
            int f = tid + l * 256;            // 0..511
            int r  = f >> 2;                  // 0..127
            int k4 = f & 3;                   // 0..3
            float4 v = *(const float4*)(Ap + (size_t)(m0 + r) * K + k0 + k4 * 4);
            As[k4 * 4 + 0][r] = v.x;
            As[k4 * 4 + 1][r] = v.y;
            As[k4 * 4 + 2][r] = v.z;
            As[k4 * 4 + 3][r] = v.w;
        }
        // Load B tile [16 x 128] -> Bs direct
#pragma unroll
        for (int l = 0; l < 2; l++) {
            int f = tid + l * 256;            // 0..511
            int kr = f >> 5;                  // 0..15
            int n4 = f & 31;                  // 0..31
            *(float4*)(&Bs[kr][n4 * 4]) =
                *(const float4*)(Bw + (size_t)(k0 + kr) * N + n0 + n4 * 4);
        }
        __syncthreads();

#pragma unroll
        for (int kk = 0; kk < 16; kk++) {
            float a[8], b[8];
#pragma unroll
            for (int i = 0; i < 8; i++) a[i] = As[kk][ty * 8 + i];
#pragma unroll
            for (int j = 0; j < 8; j++) b[j] = Bs[kk][tx * 8 + j];
#pragma unroll
            for (int i = 0; i < 8; i++)
#pragma unroll
                for (int j = 0; j < 8; j++) acc[i][j] += a[i] * b[j];
        }
        __syncthreads();
    }

    // Epilogue
#pragma unroll
    for (int i = 0; i < 8; i++) {
        int r = m0 + ty * 8 + i;
        int b = r >> 10;            // batch
        int s = r & 1023;           // seq
#pragma unroll
        for (int j = 0; j < 8; j++) {
            int c = n0 + tx * 8 + j;
            float val = acc[i][j] + bias[c];
            if (MODE == 0) {
                int h = c >> 7;         // head (2*hd = 128 per head)
                int w = c & 127;
                if (w < 64)
                    g_Q[(((size_t)(b * NH + h)) * NS + s) * HD + w] = val;
                else
                    g_K[(((size_t)(b * NH + h)) * NS + s) * HD + (w - 64)] = val;
            } else if (MODE == 1) {
                int h = c >> 6;
                int d = c & 63;
                g_V[(((size_t)(b * NH + h)) * NS + s) * HD + d] = val;
            } else {
                out[(size_t)r * N + c] = val;
            }
        }
    }
}

// ---------------------------------------------------------------------------
// Flash attention: one CTA = one (b,h) x 64-row Q tile. hd = 64.
// 256 threads: 16x16 grid, each thread 4 rows x 4 cols.
// Online softmax, scale folded into Q load. Output -> g_ctx [B,S,D].
// Dynamic smem: Qs[64][64] + KsT[64][65] + Vs[64][64] + Ps[64][64]
// ---------------------------------------------------------------------------
#define ATTN_SMEM_FLOATS (4096 + 64 * 65 + 4096 + 4096)
#define ATTN_SMEM_BYTES (ATTN_SMEM_FLOATS * 4)

__global__ __launch_bounds__(256) void attn_kernel()
{
    extern __shared__ float sh[];
    float* Qs  = sh;                         // [64][64]
    float* KsT = sh + 4096;                  // [d][j] : [64][65]
    float* Vs  = sh + 4096 + 64 * 65;        // [64][64]
    float* Ps  = sh + 4096 + 64 * 65 + 4096; // [64][64]

    const int tid = threadIdx.x;
    const int ty = tid >> 4;     // row group 0..15
    const int tx = tid & 15;     // col group 0..15
    const int i0 = ty * 4;
    const int c0 = tx * 4;

    const int qt = blockIdx.x;   // 0..15 q tile
    const int bh = blockIdx.y;   // 0..127 (b*16+h)

    const float* Qg  = g_Q + ((size_t)bh * NS + qt * 64) * HD;
    const float* Kg0 = g_K + (size_t)bh * NS * HD;
    const float* Vg0 = g_V + (size_t)bh * NS * HD;

    // Load Q tile, fold in softmax scale 1/sqrt(64) = 0.125
    for (int f = tid; f < 64 * 16; f += 256) {
        float4 v = ((const float4*)Qg)[f];
        v.x *= 0.125f; v.y *= 0.125f; v.z *= 0.125f; v.w *= 0.125f;
        ((float4*)Qs)[f] = v;
    }

    float acc[4][4];
    float Mi[4], Li[4];
#pragma unroll
    for (int ii = 0; ii < 4; ii++) {
        Mi[ii] = -1e30f;
        Li[ii] = 0.0f;
#pragma unroll
        for (int dd = 0; dd < 4; dd++) acc[ii][dd] = 0.0f;
    }

    for (int kt = 0; kt < 16; kt++) {
        const float* Kg = Kg0 + (size_t)kt * 64 * HD;
        const float* Vg = Vg0 + (size_t)kt * 64 * HD;
        // Load K (transposed into KsT[d][j]) and V
        for (int f = tid; f < 64 * 16; f += 256) {
            float4 v = ((const float4*)Kg)[f];
            int r  = f >> 4;        // key row j
            int d4 = (f & 15) * 4;  // d base
            KsT[(d4 + 0) * 65 + r] = v.x;
            KsT[(d4 + 1) * 65 + r] = v.y;
            KsT[(d4 + 2) * 65 + r] = v.z;
            KsT[(d4 + 3) * 65 + r] = v.w;
            ((float4*)Vs)[f] = ((const float4*)Vg)[f];
        }
        __syncthreads();

        // S = Q @ K^T  (scaled)
        float s[4][4];
#pragma unroll
        for (int ii = 0; ii < 4; ii++)
#pragma unroll
            for (int jj = 0; jj < 4; jj++) s[ii][jj] = 0.0f;

#pragma unroll 8
        for (int d = 0; d < 64; d++) {
            float q0 = Qs[(i0 + 0) * 64 + d];
            float q1 = Qs[(i0 + 1) * 64 + d];
            float q2 = Qs[(i0 + 2) * 64 + d];
            float q3 = Qs[(i0 + 3) * 64 + d];
            float k0 = KsT[d * 65 + c0 + 0];
            float k1 = KsT[d * 65 + c0 + 1];
            float k2 = KsT[d * 65 + c0 + 2];
            float k3 = KsT[d * 65 + c0 + 3];
            s[0][0] += q0 * k0; s[0][1] += q0 * k1; s[0][2] += q0 * k2; s[0][3] += q0 * k3;
            s[1][0] += q1 * k0; s[1][1] += q1 * k1; s[1][2] += q1 * k2; s[1][3] += q1 * k3;
            s[2][0] += q2 * k0; s[2][1] += q2 * k1; s[2][2] += q2 * k2; s[2][3] += q2 * k3;
            s[3][0] += q3 * k0; s[3][1] += q3 * k1; s[3][2] += q3 * k2; s[3][3] += q3 * k3;
        }

        // Online softmax per row (row i owned by the 16 lanes with same ty)
#pragma unroll
        for (int ii = 0; ii < 4; ii++) {
            float rm = fmaxf(fmaxf(s[ii][0], s[ii][1]), fmaxf(s[ii][2], s[ii][3]));
            rm = fmaxf(rm, __shfl_xor_sync(0xffffffffu, rm, 1, 16));
            rm = fmaxf(rm, __shfl_xor_sync(0xffffffffu, rm, 2, 16));
            rm = fmaxf(rm, __shfl_xor_sync(0xffffffffu, rm, 4, 16));
            rm = fmaxf(rm, __shfl_xor_sync(0xffffffffu, rm, 8, 16));
            float mnew = fmaxf(Mi[ii], rm);
            float fac  = __expf(Mi[ii] - mnew);
            float p0 = __expf(s[ii][0] - mnew);
            float p1 = __expf(s[ii][1] - mnew);
            float p2 = __expf(s[ii][2] - mnew);
            float p3 = __expf(s[ii][3] - mnew);
            float rs = p0 + p1 + p2 + p3;
            rs += __shfl_xor_sync(0xffffffffu, rs, 1, 16);
            rs += __shfl_xor_sync(0xffffffffu, rs, 2, 16);
            rs += __shfl_xor_sync(0xffffffffu, rs, 4, 16);
            rs += __shfl_xor_sync(0xffffffffu, rs, 8, 16);
            Li[ii] = Li[ii] * fac + rs;
            Mi[ii] = mnew;
            acc[ii][0] *= fac; acc[ii][1] *= fac; acc[ii][2] *= fac; acc[ii][3] *= fac;
            float4 pv = make_float4(p0, p1, p2, p3);
            *(float4*)(&Ps[(i0 + ii) * 64 + c0]) = pv;
        }
        __syncthreads();

        // O += P @ V    (this thread owns output cols c0..c0+3)
#pragma unroll 8
        for (int j = 0; j < 64; j++) {
            float4 vv = ((const float4*)(Vs + j * 64))[tx];
            float p0 = Ps[(i0 + 0) * 64 + j];
            float p1 = Ps[(i0 + 1) * 64 + j];
            float p2 = Ps[(i0 + 2) * 64 + j];
            float p3 = Ps[(i0 + 3) * 64 + j];
            acc[0][0] += p0 * vv.x; acc[0][1] += p0 * vv.y; acc[0][2] += p0 * vv.z; acc[0][3] += p0 * vv.w;
            acc[1][0] += p1 * vv.x; acc[1][1] += p1 * vv.y; acc[1][2] += p1 * vv.z; acc[1][3] += p1 * vv.w;
            acc[2][0] += p2 * vv.x; acc[2][1] += p2 * vv.y; acc[2][2] += p2 * vv.z; acc[2][3] += p2 * vv.w;
            acc[3][0] += p3 * vv.x; acc[3][1] += p3 * vv.y; acc[3][2] += p3 * vv.z; acc[3][3] += p3 * vv.w;
        }
        __syncthreads();
    }

    // Finalize: divide by L, write ctx [B, S, D] with D = h*64 + d
    const int b = bh >> 4;
    const int h = bh & 15;
#pragma unroll
    for (int ii = 0; ii < 4; ii++) {
        float inv = 1.0f / Li[ii];
        float4 o = make_float4(acc[ii][0] * inv, acc[ii][1] * inv,
                               acc[ii][2] * inv, acc[ii][3] * inv);
        int srow = qt * 64 + i0 + ii;
        *(float4*)(g_ctx + ((size_t)(b * NS + srow)) * ND + h * HD + c0) = o;
    }
}

// ---------------------------------------------------------------------------
extern "C" void kernel_launch(void* const* d_in, const int* in_sizes, int n_in,
                              void* d_out, int out_size)
{
    const float* in_q = (const float*)d_in[0];  // input_query  [8,1024,1024]
    const float* enc  = (const float*)d_in[1];  // encoding_output
    const float* Wqk  = (const float*)d_in[2];  // [1024, 2048]
    const float* bqk  = (const float*)d_in[3];  // [2048]
    const float* Wv   = (const float*)d_in[4];  // [1024, 1024]
    const float* bv   = (const float*)d_in[5];  // [1024]
    const float* Wo   = (const float*)d_in[6];  // [1024, 1024]
    const float* bo   = (const float*)d_in[7];  // [1024]
    float* out = (float*)d_out;

    cudaFuncSetAttribute(attn_kernel,
                         cudaFuncAttributeMaxDynamicSharedMemorySize,
                         ATTN_SMEM_BYTES);

    // 1) QK projection: [8192,1024] @ [1024,2048] -> Q,K scatter
    gemm_f32<0><<<dim3(2048 / 128, 8192 / 128), 256>>>(enc, Wqk, bqk, nullptr, 1024, 2048);
    // 2) V projection: [8192,1024] @ [1024,1024] -> V scatter
    gemm_f32<1><<<dim3(1024 / 128, 8192 / 128), 256>>>(in_q, Wv, bv, nullptr, 1024, 1024);
    // 3) Flash attention: grid = (16 q-tiles, 128 b*h)
    attn_kernel<<<dim3(16, 128), 256, ATTN_SMEM_BYTES>>>();
    // 4) Output projection: ctx @ Wo + bo -> out
    gemm_f32<2><<<dim3(1024 / 128, 8192 / 128), 256>>>(nullptr, Wo, bo, out, 1024, 1024);
}

// round 4
// speedup vs baseline: 1.4707x; 1.4707x over previous
#include <cuda_runtime.h>
#include <math.h>
#include <stdint.h>

// Problem constants: B=8, S=1024, D=1024, H=16, hd=64
#define NB 8
#define NS 1024
#define ND 1024
#define NH 16
#define HD 64

// Scratch (allocation-free rule: __device__ globals)
__device__ float g_Q[NB * NH * NS * HD];   // [B,H,S,hd]
__device__ float g_K[NB * NH * NS * HD];
__device__ float g_V[NB * NH * NS * HD];
__device__ float g_ctx[NB * NS * ND];      // [B,S,D]

// tf32 lives in a b32 container: cvt dst must be a .b32 register.
__device__ __forceinline__ uint32_t to_tf32(float x) {
    uint32_t r;
    asm("cvt.rna.tf32.f32 %0, %1;" : "=r"(r) : "f"(x));
    return r;
}

__device__ __forceinline__ void mma_tf32(float c[4], const uint32_t a[4], const uint32_t b[2]) {
    asm volatile(
        "mma.sync.aligned.m16n8k8.row.col.f32.tf32.tf32.f32 "
        "{%0,%1,%2,%3}, {%4,%5,%6,%7}, {%8,%9}, {%0,%1,%2,%3};"
        : "+f"(c[0]), "+f"(c[1]), "+f"(c[2]), "+f"(c[3])
        : "r"(a[0]), "r"(a[1]), "r"(a[2]), "r"(a[3]), "r"(b[0]), "r"(b[1]));
}

// ---------------------------------------------------------------------------
// tf32 tensor-core GEMM: C[M,N] = A[M,K] @ B[K,N] + bias
// BM=BN=128, BK=32, 256 threads = 8 warps (2 x 4), warp tile 64x32,
// per-warp 4x4 grid of m16n8k8 mma. Register-prefetch global pipeline.
// MODE 0: QK projection epilogue -> scatter to g_Q / g_K  (N=2048)
// MODE 1: V  projection epilogue -> scatter to g_V        (N=1024)
// MODE 2: plain epilogue, A taken from g_ctx, out = d_out (N=1024)
// M = 8192, K = 1024 in all cases (no bounds checks needed).
// ---------------------------------------------------------------------------
template <int MODE>
__global__ __launch_bounds__(256) void gemm_tf32(
    const float* __restrict__ A, const float* __restrict__ Bw,
    const float* __restrict__ bias, float* __restrict__ out,
    int K, int N)
{
    __shared__ uint32_t As[32 * 132];   // [k][m] tf32 bits, padded stride 132
    __shared__ uint32_t Bs[32 * 132];   // [k][n] tf32 bits, padded stride 132

    const int tid  = threadIdx.x;
    const int lane = tid & 31;
    const int warp = tid >> 5;
    const int g    = lane >> 2;      // groupID 0..7
    const int tig  = lane & 3;       // thread in group 0..3
    const int warpM = warp >> 2;     // 0..1
    const int warpN = warp & 3;      // 0..3
    const int wm0 = warpM * 64;
    const int wn0 = warpN * 32;

    const int m0 = blockIdx.y * 128;
    const int n0 = blockIdx.x * 128;

    const float* Ap = (MODE == 2) ? (const float*)g_ctx : A;

    // Global-load addressing
    const int ra = tid >> 3;         // 0..31  (A row base, +32 per l)
    const int kc = (tid & 7) * 4;    // 0..28  (A k column base)
    const int kr0 = tid >> 5;        // 0..7   (B k row base, +8 per l)
    const int nb4 = (tid & 31) * 4;  // 0..124 (B n column base)

    const float* Aldg = Ap + (size_t)(m0 + ra) * K + kc;
    const float* Bldg = Bw + (size_t)kr0 * N + n0 + nb4;

    float acc[4][4][4];
#pragma unroll
    for (int mt = 0; mt < 4; mt++)
#pragma unroll
        for (int nt = 0; nt < 4; nt++)
#pragma unroll
            for (int e = 0; e < 4; e++) acc[mt][nt][e] = 0.0f;

    float4 pa[4], pb[4];

    // Prologue: load tile 0
#pragma unroll
    for (int l = 0; l < 4; l++) {
        pa[l] = *(const float4*)(Aldg + (size_t)(l * 32) * K);
        pb[l] = *(const float4*)(Bldg + (size_t)(l * 8) * N);
    }
    // Store tile 0 to smem (convert to tf32 bits)
#pragma unroll
    for (int l = 0; l < 4; l++) {
        As[(kc + 0) * 132 + ra + 32 * l] = to_tf32(pa[l].x);
        As[(kc + 1) * 132 + ra + 32 * l] = to_tf32(pa[l].y);
        As[(kc + 2) * 132 + ra + 32 * l] = to_tf32(pa[l].z);
        As[(kc + 3) * 132 + ra + 32 * l] = to_tf32(pa[l].w);
        uint4 t;
        t.x = to_tf32(pb[l].x); t.y = to_tf32(pb[l].y);
        t.z = to_tf32(pb[l].z); t.w = to_tf32(pb[l].w);
        *(uint4*)(&Bs[(kr0 + 8 * l) * 132 + nb4]) = t;
    }
    __syncthreads();

    for (int k0 = 0; k0 < K; k0 += 32) {
        const bool more = (k0 + 32 < K);
        if (more) {
#pragma unroll
            for (int l = 0; l < 4; l++) {
                pa[l] = *(const float4*)(Aldg + (size_t)(l * 32) * K + (k0 + 32));
                pb[l] = *(const float4*)(Bldg + (size_t)((k0 + 32) + l * 8) * N);
            }
        }

        // Compute on current smem tile: 4 k8-steps
#pragma unroll
        for (int ks = 0; ks < 4; ks++) {
            const int k8 = ks * 8;
            uint32_t af[4][4], bf[4][2];
#pragma unroll
            for (int mt = 0; mt < 4; mt++) {
                const int rb = wm0 + mt * 16 + g;
                af[mt][0] = As[(k8 + tig) * 132 + rb];
                af[mt][1] = As[(k8 + tig) * 132 + rb + 8];
                af[mt][2] = As[(k8 + tig + 4) * 132 + rb];
                af[mt][3] = As[(k8 + tig + 4) * 132 + rb + 8];
            }
#pragma unroll
            for (int nt = 0; nt < 4; nt++) {
                const int cb = wn0 + nt * 8 + g;
                bf[nt][0] = Bs[(k8 + tig) * 132 + cb];
                bf[nt][1] = Bs[(k8 + tig + 4) * 132 + cb];
            }
#pragma unroll
            for (int mt = 0; mt < 4; mt++)
#pragma unroll
                for (int nt = 0; nt < 4; nt++)
                    mma_tf32(acc[mt][nt], af[mt], bf[nt]);
        }
        __syncthreads();

        if (more) {
#pragma unroll
            for (int l = 0; l < 4; l++) {
                As[(kc + 0) * 132 + ra + 32 * l] = to_tf32(pa[l].x);
                As[(kc + 1) * 132 + ra + 32 * l] = to_tf32(pa[l].y);
                As[(kc + 2) * 132 + ra + 32 * l] = to_tf32(pa[l].z);
                As[(kc + 3) * 132 + ra + 32 * l] = to_tf32(pa[l].w);
                uint4 t;
                t.x = to_tf32(pb[l].x); t.y = to_tf32(pb[l].y);
                t.z = to_tf32(pb[l].z); t.w = to_tf32(pb[l].w);
                *(uint4*)(&Bs[(kr0 + 8 * l) * 132 + nb4]) = t;
            }
            __syncthreads();
        }
    }

    // Epilogue: c-fragment (mt,nt) covers rows {r0, r0+8}, cols {c0, c0+1}
#pragma unroll
    for (int mt = 0; mt < 4; mt++) {
        const int rbase = m0 + wm0 + mt * 16 + g;
#pragma unroll
        for (int nt = 0; nt < 4; nt++) {
            const int cbase = n0 + wn0 + nt * 8 + tig * 2;
#pragma unroll
            for (int e = 0; e < 4; e++) {
                const int r = rbase + (e >> 1) * 8;
                const int c = cbase + (e & 1);
                const float val = acc[mt][nt][e] + bias[c];
                const int b = r >> 10;
                const int s = r & 1023;
                if (MODE == 0) {
                    const int h = c >> 7;
                    const int w = c & 127;
                    if (w < 64)
                        g_Q[(((size_t)(b * NH + h)) * NS + s) * HD + w] = val;
                    else
                        g_K[(((size_t)(b * NH + h)) * NS + s) * HD + (w - 64)] = val;
                } else if (MODE == 1) {
                    const int h = c >> 6;
                    const int d = c & 63;
                    g_V[(((size_t)(b * NH + h)) * NS + s) * HD + d] = val;
                } else {
                    out[(size_t)r * N + c] = val;
                }
            }
        }
    }
}

// ---------------------------------------------------------------------------
// Flash attention: one CTA = one (b,h) x 64-row Q tile. hd = 64. (unchanged)
// ---------------------------------------------------------------------------
#define ATTN_SMEM_FLOATS (4096 + 64 * 65 + 4096 + 4096)
#define ATTN_SMEM_BYTES (ATTN_SMEM_FLOATS * 4)

__global__ __launch_bounds__(256) void attn_kernel()
{
    extern __shared__ float sh[];
    float* Qs  = sh;                         // [64][64]
    float* KsT = sh + 4096;                  // [d][j] : [64][65]
    float* Vs  = sh + 4096 + 64 * 65;        // [64][64]
    float* Ps  = sh + 4096 + 64 * 65 + 4096; // [64][64]

    const int tid = threadIdx.x;
    const int ty = tid >> 4;     // row group 0..15
    const int tx = tid & 15;     // col group 0..15
    const int i0 = ty * 4;
    const int c0 = tx * 4;

    const int qt = blockIdx.x;   // 0..15 q tile
    const int bh = blockIdx.y;   // 0..127 (b*16+h)

    const float* Qg  = g_Q + ((size_t)bh * NS + qt * 64) * HD;
    const float* Kg0 = g_K + (size_t)bh * NS * HD;
    const float* Vg0 = g_V + (size_t)bh * NS * HD;

    // Load Q tile, fold in softmax scale 1/sqrt(64) = 0.125
    for (int f = tid; f < 64 * 16; f += 256) {
        float4 v = ((const float4*)Qg)[f];
        v.x *= 0.125f; v.y *= 0.125f; v.z *= 0.125f; v.w *= 0.125f;
        ((float4*)Qs)[f] = v;
    }

    float acc[4][4];
    float Mi[4], Li[4];
#pragma unroll
    for (int ii = 0; ii < 4; ii++) {
        Mi[ii] = -1e30f;
        Li[ii] = 0.0f;
#pragma unroll
        for (int dd = 0; dd < 4; dd++) acc[ii][dd] = 0.0f;
    }

    for (int kt = 0; kt < 16; kt++) {
        const float* Kg = Kg0 + (size_t)kt * 64 * HD;
        const float* Vg = Vg0 + (size_t)kt * 64 * HD;
        for (int f = tid; f < 64 * 16; f += 256) {
            float4 v = ((const float4*)Kg)[f];
            int r  = f >> 4;        // key row j
            int d4 = (f & 15) * 4;  // d base
            KsT[(d4 + 0) * 65 + r] = v.x;
            KsT[(d4 + 1) * 65 + r] = v.y;
            KsT[(d4 + 2) * 65 + r] = v.z;
            KsT[(d4 + 3) * 65 + r] = v.w;
            ((float4*)Vs)[f] = ((const float4*)Vg)[f];
        }
        __syncthreads();

        float s[4][4];
#pragma unroll
        for (int ii = 0; ii < 4; ii++)
#pragma unroll
            for (int jj = 0; jj < 4; jj++) s[ii][jj] = 0.0f;

#pragma unroll 8
        for (int d = 0; d < 64; d++) {
            float q0 = Qs[(i0 + 0) * 64 + d];
            float q1 = Qs[(i0 + 1) * 64 + d];
            float q2 = Qs[(i0 + 2) * 64 + d];
            float q3 = Qs[(i0 + 3) * 64 + d];
            float k0 = KsT[d * 65 + c0 + 0];
            float k1 = KsT[d * 65 + c0 + 1];
            float k2 = KsT[d * 65 + c0 + 2];
            float k3 = KsT[d * 65 + c0 + 3];
            s[0][0] += q0 * k0; s[0][1] += q0 * k1; s[0][2] += q0 * k2; s[0][3] += q0 * k3;
            s[1][0] += q1 * k0; s[1][1] += q1 * k1; s[1][2] += q1 * k2; s[1][3] += q1 * k3;
            s[2][0] += q2 * k0; s[2][1] += q2 * k1; s[2][2] += q2 * k2; s[2][3] += q2 * k3;
            s[3][0] += q3 * k0; s[3][1] += q3 * k1; s[3][2] += q3 * k2; s[3][3] += q3 * k3;
        }

#pragma unroll
        for (int ii = 0; ii < 4; ii++) {
            float rm = fmaxf(fmaxf(s[ii][0], s[ii][1]), fmaxf(s[ii][2], s[ii][3]));
            rm = fmaxf(rm, __shfl_xor_sync(0xffffffffu, rm, 1, 16));
            rm = fmaxf(rm, __shfl_xor_sync(0xffffffffu, rm, 2, 16));
            rm = fmaxf(rm, __shfl_xor_sync(0xffffffffu, rm, 4, 16));
            rm = fmaxf(rm, __shfl_xor_sync(0xffffffffu, rm, 8, 16));
            float mnew = fmaxf(Mi[ii], rm);
            float fac  = __expf(Mi[ii] - mnew);
            float p0 = __expf(s[ii][0] - mnew);
            float p1 = __expf(s[ii][1] - mnew);
            float p2 = __expf(s[ii][2] - mnew);
            float p3 = __expf(s[ii][3] - mnew);
            float rs = p0 + p1 + p2 + p3;
            rs += __shfl_xor_sync(0xffffffffu, rs, 1, 16);
            rs += __shfl_xor_sync(0xffffffffu, rs, 2, 16);
            rs += __shfl_xor_sync(0xffffffffu, rs, 4, 16);
            rs += __shfl_xor_sync(0xffffffffu, rs, 8, 16);
            Li[ii] = Li[ii] * fac + rs;
            Mi[ii] = mnew;
            acc[ii][0] *= fac; acc[ii][1] *= fac; acc[ii][2] *= fac; acc[ii][3] *= fac;
            float4 pv = make_float4(p0, p1, p2, p3);
            *(float4*)(&Ps[(i0 + ii) * 64 + c0]) = pv;
        }
        __syncthreads();

#pragma unroll 8
        for (int j = 0; j < 64; j++) {
            float4 vv = ((const float4*)(Vs + j * 64))[tx];
            float p0 = Ps[(i0 + 0) * 64 + j];
            float p1 = Ps[(i0 + 1) * 64 + j];
            float p2 = Ps[(i0 + 2) * 64 + j];
            float p3 = Ps[(i0 + 3) * 64 + j];
            acc[0][0] += p0 * vv.x; acc[0][1] += p0 * vv.y; acc[0][2] += p0 * vv.z; acc[0][3] += p0 * vv.w;
            acc[1][0] += p1 * vv.x; acc[1][1] += p1 * vv.y; acc[1][2] += p1 * vv.z; acc[1][3] += p1 * vv.w;
            acc[2][0] += p2 * vv.x; acc[2][1] += p2 * vv.y; acc[2][2] += p2 * vv.z; acc[2][3] += p2 * vv.w;
            acc[3][0] += p3 * vv.x; acc[3][1] += p3 * vv.y; acc[3][2] += p3 * vv.z; acc[3][3] += p3 * vv.w;
        }
        __syncthreads();
    }

    const int b = bh >> 4;
    const int h = bh & 15;
#pragma unroll
    for (int ii = 0; ii < 4; ii++) {
        float inv = 1.0f / Li[ii];
        float4 o = make_float4(acc[ii][0] * inv, acc[ii][1] * inv,
                               acc[ii][2] * inv, acc[ii][3] * inv);
        int srow = qt * 64 + i0 + ii;
        *(float4*)(g_ctx + ((size_t)(b * NS + srow)) * ND + h * HD + c0) = o;
    }
}

// ---------------------------------------------------------------------------
extern "C" void kernel_launch(void* const* d_in, const int* in_sizes, int n_in,
                              void* d_out, int out_size)
{
    const float* in_q = (const float*)d_in[0];  // input_query  [8,1024,1024]
    const float* enc  = (const float*)d_in[1];  // encoding_output
    const float* Wqk  = (const float*)d_in[2];  // [1024, 2048]
    const float* bqk  = (const float*)d_in[3];  // [2048]
    const float* Wv   = (const float*)d_in[4];  // [1024, 1024]
    const float* bv   = (const float*)d_in[5];  // [1024]
    const float* Wo   = (const float*)d_in[6];  // [1024, 1024]
    const float* bo   = (const float*)d_in[7];  // [1024]
    float* out = (float*)d_out;

    cudaFuncSetAttribute(attn_kernel,
                         cudaFuncAttributeMaxDynamicSharedMemorySize,
                         ATTN_SMEM_BYTES);

    // 1) QK projection: [8192,1024] @ [1024,2048] -> Q,K scatter
    gemm_tf32<0><<<dim3(2048 / 128, 8192 / 128), 256>>>(enc, Wqk, bqk, nullptr, 1024, 2048);
    // 2) V projection: [8192,1024] @ [1024,1024] -> V scatter
    gemm_tf32<1><<<dim3(1024 / 128, 8192 / 128), 256>>>(in_q, Wv, bv, nullptr, 1024, 1024);
    // 3) Flash attention: grid = (16 q-tiles, 128 b*h)
    attn_kernel<<<dim3(16, 128), 256, ATTN_SMEM_BYTES>>>();
    // 4) Output projection: ctx @ Wo + bo -> out
    gemm_tf32<2><<<dim3(1024 / 128, 8192 / 128), 256>>>(nullptr, Wo, bo, out, 1024, 1024);
}

// round 7
// speedup vs baseline: 2.4347x; 1.6555x over previous
#include <cuda_runtime.h>
#include <math.h>
#include <stdint.h>

// Problem constants: B=8, S=1024, D=1024, H=16, hd=64
#define NB 8
#define NS 1024
#define ND 1024
#define NH 16
#define HD 64

// Scratch (allocation-free rule: __device__ globals)
__device__ float g_Q[NB * NH * NS * HD];   // [B,H,S,hd]
__device__ float g_K[NB * NH * NS * HD];
__device__ float g_V[NB * NH * NS * HD];
__device__ float g_ctx[NB * NS * ND];      // [B,S,D]

// tf32 lives in a b32 container: cvt dst must be a .b32 register.
__device__ __forceinline__ uint32_t to_tf32(float x) {
    uint32_t r;
    asm("cvt.rna.tf32.f32 %0, %1;" : "=r"(r) : "f"(x));
    return r;
}

__device__ __forceinline__ void mma_tf32(float c[4], const uint32_t a[4], const uint32_t b[2]) {
    asm volatile(
        "mma.sync.aligned.m16n8k8.row.col.f32.tf32.tf32.f32 "
        "{%0,%1,%2,%3}, {%4,%5,%6,%7}, {%8,%9}, {%0,%1,%2,%3};"
        : "+f"(c[0]), "+f"(c[1]), "+f"(c[2]), "+f"(c[3])
        : "r"(a[0]), "r"(a[1]), "r"(a[2]), "r"(a[3]), "r"(b[0]), "r"(b[1]));
}

// ---------------------------------------------------------------------------
// tf32 tensor-core GEMM, double-buffered DYNAMIC smem: C = A @ B + bias
// BM=BN=128, BK=32, 256 threads = 8 warps (2 x 4), warp tile 64x32.
// Dynamic smem: As[2][32*132] then Bs[2][32*132]  (67584 bytes total).
// ---------------------------------------------------------------------------
#define TILE_U32 (32 * 132)
#define GEMM_SMEM_BYTES (4 * TILE_U32 * 4)   // 2 bufs x (A+B) x 4B = 67584

template <int MODE>
__global__ __launch_bounds__(256) void gemm_tf32(
    const float* __restrict__ A, const float* __restrict__ Bw,
    const float* __restrict__ bias, float* __restrict__ out,
    int K, int N)
{
    extern __shared__ uint32_t dynsh[];
    uint32_t* As = dynsh;                    // [buf][k][m] tf32 bits, stride 132
    uint32_t* Bs = dynsh + 2 * TILE_U32;     // [buf][k][n]

    const int tid  = threadIdx.x;
    const int lane = tid & 31;
    const int warp = tid >> 5;
    const int g    = lane >> 2;      // groupID 0..7
    const int tig  = lane & 3;       // thread in group 0..3
    const int wm0 = (warp >> 2) * 64;
    const int wn0 = (warp & 3) * 32;

    const int m0 = blockIdx.y * 128;
    const int n0 = blockIdx.x * 128;

    const float* Ap = (MODE == 2) ? (const float*)g_ctx : A;

    const int ra = tid >> 3;         // 0..31  (A row base, +32 per l)
    const int kc = (tid & 7) * 4;    // 0..28  (A k column base)
    const int kr0 = tid >> 5;        // 0..7   (B k row base, +8 per l)
    const int nb4 = (tid & 31) * 4;  // 0..124 (B n column base)

    const float* Aldg = Ap + (size_t)(m0 + ra) * K + kc;
    const float* Bldg = Bw + (size_t)kr0 * N + n0 + nb4;

    float acc[4][4][4];
#pragma unroll
    for (int mt = 0; mt < 4; mt++)
#pragma unroll
        for (int nt = 0; nt < 4; nt++)
#pragma unroll
            for (int e = 0; e < 4; e++) acc[mt][nt][e] = 0.0f;

    float4 pa[4], pb[4];

    // Prologue: load + store tile 0 into buf 0
#pragma unroll
    for (int l = 0; l < 4; l++) {
        pa[l] = *(const float4*)(Aldg + (size_t)(l * 32) * K);
        pb[l] = *(const float4*)(Bldg + (size_t)(l * 8) * N);
    }
#pragma unroll
    for (int l = 0; l < 4; l++) {
        As[(kc + 0) * 132 + ra + 32 * l] = to_tf32(pa[l].x);
        As[(kc + 1) * 132 + ra + 32 * l] = to_tf32(pa[l].y);
        As[(kc + 2) * 132 + ra + 32 * l] = to_tf32(pa[l].z);
        As[(kc + 3) * 132 + ra + 32 * l] = to_tf32(pa[l].w);
        uint4 t;
        t.x = to_tf32(pb[l].x); t.y = to_tf32(pb[l].y);
        t.z = to_tf32(pb[l].z); t.w = to_tf32(pb[l].w);
        *(uint4*)(&Bs[(kr0 + 8 * l) * 132 + nb4]) = t;
    }
    __syncthreads();

    int buf = 0;
    for (int k0 = 0; k0 < K; k0 += 32) {
        const bool more = (k0 + 32 < K);
        if (more) {
#pragma unroll
            for (int l = 0; l < 4; l++) {
                pa[l] = *(const float4*)(Aldg + (size_t)(l * 32) * K + (k0 + 32));
                pb[l] = *(const float4*)(Bldg + (size_t)((k0 + 32) + l * 8) * N);
            }
        }

        const uint32_t* Ab = As + buf * TILE_U32;
        const uint32_t* Bb = Bs + buf * TILE_U32;
#pragma unroll
        for (int ks = 0; ks < 4; ks++) {
            const int k8 = ks * 8;
            uint32_t af[4][4], bf[4][2];
#pragma unroll
            for (int mt = 0; mt < 4; mt++) {
                const int rb = wm0 + mt * 16 + g;
                af[mt][0] = Ab[(k8 + tig) * 132 + rb];
                af[mt][1] = Ab[(k8 + tig) * 132 + rb + 8];
                af[mt][2] = Ab[(k8 + tig + 4) * 132 + rb];
                af[mt][3] = Ab[(k8 + tig + 4) * 132 + rb + 8];
            }
#pragma unroll
            for (int nt = 0; nt < 4; nt++) {
                const int cb = wn0 + nt * 8 + g;
                bf[nt][0] = Bb[(k8 + tig) * 132 + cb];
                bf[nt][1] = Bb[(k8 + tig + 4) * 132 + cb];
            }
#pragma unroll
            for (int mt = 0; mt < 4; mt++)
#pragma unroll
                for (int nt = 0; nt < 4; nt++)
                    mma_tf32(acc[mt][nt], af[mt], bf[nt]);
        }

        if (more) {
            uint32_t* An = As + (buf ^ 1) * TILE_U32;
            uint32_t* Bn = Bs + (buf ^ 1) * TILE_U32;
#pragma unroll
            for (int l = 0; l < 4; l++) {
                An[(kc + 0) * 132 + ra + 32 * l] = to_tf32(pa[l].x);
                An[(kc + 1) * 132 + ra + 32 * l] = to_tf32(pa[l].y);
                An[(kc + 2) * 132 + ra + 32 * l] = to_tf32(pa[l].z);
                An[(kc + 3) * 132 + ra + 32 * l] = to_tf32(pa[l].w);
                uint4 t;
                t.x = to_tf32(pb[l].x); t.y = to_tf32(pb[l].y);
                t.z = to_tf32(pb[l].z); t.w = to_tf32(pb[l].w);
                *(uint4*)(&Bn[(kr0 + 8 * l) * 132 + nb4]) = t;
            }
            __syncthreads();
            buf ^= 1;
        }
    }

    // Epilogue
#pragma unroll
    for (int mt = 0; mt < 4; mt++) {
        const int rbase = m0 + wm0 + mt * 16 + g;
#pragma unroll
        for (int nt = 0; nt < 4; nt++) {
            const int cbase = n0 + wn0 + nt * 8 + tig * 2;
#pragma unroll
            for (int e = 0; e < 4; e++) {
                const int r = rbase + (e >> 1) * 8;
                const int c = cbase + (e & 1);
                const float val = acc[mt][nt][e] + bias[c];
                const int b = r >> 10;
                const int s = r & 1023;
                if (MODE == 0) {
                    const int h = c >> 7;
                    const int w = c & 127;
                    if (w < 64)
                        g_Q[(((size_t)(b * NH + h)) * NS + s) * HD + w] = val;
                    else
                        g_K[(((size_t)(b * NH + h)) * NS + s) * HD + (w - 64)] = val;
                } else if (MODE == 1) {
                    const int h = c >> 6;
                    const int d = c & 63;
                    g_V[(((size_t)(b * NH + h)) * NS + s) * HD + d] = val;
                } else {
                    out[(size_t)r * N + c] = val;
                }
            }
        }
    }
}

// ---------------------------------------------------------------------------
// Flash attention on tensor cores (tf32 mma.m16n8k8).
// CTA = 128 threads = 4 warps. Q tile = 64 rows (16 per warp). K tile = 64.
// Key layout trick: mma row.col B operand = col-major-in-k = K stored [seq][d]
// and V stored [seq][d] -> NO smem transpose needed for either GEMM.
// Online softmax lives in C-fragments (rows g, g+8); reduction = 2 shfls.
// P goes through per-warp smem region (syncwarp only).
// ---------------------------------------------------------------------------
#define QS_STR 68
#define KS_STR 68
#define VS_STR 72
#define PS_STR 68
#define QS_OFF 0
#define KS_OFF (64 * QS_STR)                       // 4352
#define VS_OFF (KS_OFF + 64 * KS_STR)              // 8704
#define PS_OFF (VS_OFF + 64 * VS_STR)              // 13312
#define ATTN_SMEM_U32 (PS_OFF + 64 * PS_STR)       // 17664
#define ATTN_SMEM_BYTES (ATTN_SMEM_U32 * 4)        // 70656

__global__ __launch_bounds__(128) void attn_kernel()
{
    extern __shared__ uint32_t sh[];
    uint32_t* Qs = sh + QS_OFF;   // [row][d]   stride 68
    uint32_t* Ks = sh + KS_OFF;   // [seq][d]   stride 68
    uint32_t* Vs = sh + VS_OFF;   // [seq][d]   stride 72
    uint32_t* Ps = sh + PS_OFF;   // [row][seq] stride 68

    const int tid  = threadIdx.x;
    const int lane = tid & 31;
    const int warp = tid >> 5;          // 0..3
    const int g    = lane >> 2;         // 0..7
    const int tig  = lane & 3;          // 0..3
    const int wrow = warp * 16;         // warp's Q-row base within tile

    const int qt = blockIdx.x;          // 0..15 q tile
    const int bh = blockIdx.y;          // 0..127

    const float* Qg  = g_Q + ((size_t)bh * NS + qt * 64) * HD;
    const float* Kg0 = g_K + (size_t)bh * NS * HD;
    const float* Vg0 = g_V + (size_t)bh * NS * HD;

    // Load Q tile once: fold softmax scale 0.125, convert to tf32.
    for (int f = tid; f < 1024; f += 128) {          // 1024 float4
        const int row = f >> 4;
        const int d4  = (f & 15) << 2;
        float4 v = *(const float4*)(Qg + row * HD + d4);
        uint4 t;
        t.x = to_tf32(v.x * 0.125f); t.y = to_tf32(v.y * 0.125f);
        t.z = to_tf32(v.z * 0.125f); t.w = to_tf32(v.w * 0.125f);
        *(uint4*)(&Qs[row * QS_STR + d4]) = t;
    }

    float oacc[8][4];                    // [d-tile][frag]
#pragma unroll
    for (int nt = 0; nt < 8; nt++)
#pragma unroll
        for (int e = 0; e < 4; e++) oacc[nt][e] = 0.0f;
    float M0 = -1e30f, M1 = -1e30f, L0 = 0.0f, L1 = 0.0f;

    for (int kt = 0; kt < 16; kt++) {
        const float* Kg = Kg0 + (size_t)kt * 64 * HD;
        const float* Vg = Vg0 + (size_t)kt * 64 * HD;
        __syncthreads();                 // protect Ks/Vs from previous iter readers
        for (int f = tid; f < 1024; f += 128) {
            const int row = f >> 4;
            const int d4  = (f & 15) << 2;
            float4 kv = *(const float4*)(Kg + row * HD + d4);
            float4 vv = *(const float4*)(Vg + row * HD + d4);
            uint4 tk, tv;
            tk.x = to_tf32(kv.x); tk.y = to_tf32(kv.y);
            tk.z = to_tf32(kv.z); tk.w = to_tf32(kv.w);
            tv.x = to_tf32(vv.x); tv.y = to_tf32(vv.y);
            tv.z = to_tf32(vv.z); tv.w = to_tf32(vv.w);
            *(uint4*)(&Ks[row * KS_STR + d4]) = tk;
            *(uint4*)(&Vs[row * VS_STR + d4]) = tv;
        }
        __syncthreads();

        // ---- S = Q @ K^T : 16x64 per warp, k over d (8 steps) ----
        float sacc[8][4];
#pragma unroll
        for (int nt = 0; nt < 8; nt++)
#pragma unroll
            for (int e = 0; e < 4; e++) sacc[nt][e] = 0.0f;

#pragma unroll
        for (int ks = 0; ks < 8; ks++) {
            const int k8 = ks * 8;
            uint32_t af[4];
            af[0] = Qs[(wrow + g)     * QS_STR + k8 + tig];
            af[1] = Qs[(wrow + g + 8) * QS_STR + k8 + tig];
            af[2] = Qs[(wrow + g)     * QS_STR + k8 + tig + 4];
            af[3] = Qs[(wrow + g + 8) * QS_STR + k8 + tig + 4];
#pragma unroll
            for (int nt = 0; nt < 8; nt++) {
                uint32_t bf[2];
                bf[0] = Ks[(nt * 8 + g) * KS_STR + k8 + tig];
                bf[1] = Ks[(nt * 8 + g) * KS_STR + k8 + tig + 4];
                mma_tf32(sacc[nt], af, bf);
            }
        }

        // ---- online softmax on fragments (rows g and g+8) ----
        float rm0 = -1e30f, rm1 = -1e30f;
#pragma unroll
        for (int nt = 0; nt < 8; nt++) {
            rm0 = fmaxf(rm0, fmaxf(sacc[nt][0], sacc[nt][1]));
            rm1 = fmaxf(rm1, fmaxf(sacc[nt][2], sacc[nt][3]));
        }
        rm0 = fmaxf(rm0, __shfl_xor_sync(0xffffffffu, rm0, 1));
        rm0 = fmaxf(rm0, __shfl_xor_sync(0xffffffffu, rm0, 2));
        rm1 = fmaxf(rm1, __shfl_xor_sync(0xffffffffu, rm1, 1));
        rm1 = fmaxf(rm1, __shfl_xor_sync(0xffffffffu, rm1, 2));

        const float mn0 = fmaxf(M0, rm0);
        const float mn1 = fmaxf(M1, rm1);
        const float fac0 = __expf(M0 - mn0);
        const float fac1 = __expf(M1 - mn1);
        float rs0 = 0.0f, rs1 = 0.0f;
#pragma unroll
        for (int nt = 0; nt < 8; nt++) {
            float p0 = __expf(sacc[nt][0] - mn0);
            float p1 = __expf(sacc[nt][1] - mn0);
            float p2 = __expf(sacc[nt][2] - mn1);
            float p3 = __expf(sacc[nt][3] - mn1);
            rs0 += p0 + p1;
            rs1 += p2 + p3;
            uint2 u0, u1;
            u0.x = to_tf32(p0); u0.y = to_tf32(p1);
            u1.x = to_tf32(p2); u1.y = to_tf32(p3);
            *(uint2*)(&Ps[(wrow + g)     * PS_STR + nt * 8 + 2 * tig]) = u0;
            *(uint2*)(&Ps[(wrow + g + 8) * PS_STR + nt * 8 + 2 * tig]) = u1;
        }
        rs0 += __shfl_xor_sync(0xffffffffu, rs0, 1);
        rs0 += __shfl_xor_sync(0xffffffffu, rs0, 2);
        rs1 += __shfl_xor_sync(0xffffffffu, rs1, 1);
        rs1 += __shfl_xor_sync(0xffffffffu, rs1, 2);
        L0 = L0 * fac0 + rs0;
        L1 = L1 * fac1 + rs1;
        M0 = mn0; M1 = mn1;
#pragma unroll
        for (int nt = 0; nt < 8; nt++) {
            oacc[nt][0] *= fac0; oacc[nt][1] *= fac0;
            oacc[nt][2] *= fac1; oacc[nt][3] *= fac1;
        }
        __syncwarp();                   // Ps region is per-warp; warp-fence enough

        // ---- O += P @ V : k over keys (8 steps), n over d (8 tiles) ----
#pragma unroll
        for (int ks = 0; ks < 8; ks++) {
            const int k8 = ks * 8;
            uint32_t af[4];
            af[0] = Ps[(wrow + g)     * PS_STR + k8 + tig];
            af[1] = Ps[(wrow + g + 8) * PS_STR + k8 + tig];
            af[2] = Ps[(wrow + g)     * PS_STR + k8 + tig + 4];
            af[3] = Ps[(wrow + g + 8) * PS_STR + k8 + tig + 4];
#pragma unroll
            for (int nt = 0; nt < 8; nt++) {
                uint32_t bf[2];
                bf[0] = Vs[(k8 + tig)     * VS_STR + nt * 8 + g];
                bf[1] = Vs[(k8 + tig + 4) * VS_STR + nt * 8 + g];
                mma_tf32(oacc[nt], af, bf);
            }
        }
        __syncwarp();                   // done reading Ps before next overwrite
    }

    // Finalize: divide by L, write ctx [B,S,D]  (D col = h*64 + d)
    const int b = bh >> 4;
    const int h = bh & 15;
    const float inv0 = 1.0f / L0;
    const float inv1 = 1.0f / L1;
    const int sr0 = qt * 64 + wrow + g;
    float* out0 = g_ctx + ((size_t)(b * NS + sr0))     * ND + h * HD;
    float* out1 = g_ctx + ((size_t)(b * NS + sr0 + 8)) * ND + h * HD;
#pragma unroll
    for (int nt = 0; nt < 8; nt++) {
        const int c = nt * 8 + 2 * tig;
        *(float2*)(out0 + c) = make_float2(oacc[nt][0] * inv0, oacc[nt][1] * inv0);
        *(float2*)(out1 + c) = make_float2(oacc[nt][2] * inv1, oacc[nt][3] * inv1);
    }
}

// ---------------------------------------------------------------------------
extern "C" void kernel_launch(void* const* d_in, const int* in_sizes, int n_in,
                              void* d_out, int out_size)
{
    const float* in_q = (const float*)d_in[0];
    const float* enc  = (const float*)d_in[1];
    const float* Wqk  = (const float*)d_in[2];
    const float* bqk  = (const float*)d_in[3];
    const float* Wv   = (const float*)d_in[4];
    const float* bv   = (const float*)d_in[5];
    const float* Wo   = (const float*)d_in[6];
    const float* bo   = (const float*)d_in[7];
    float* out = (float*)d_out;

    cudaFuncSetAttribute(gemm_tf32<0>,
                         cudaFuncAttributeMaxDynamicSharedMemorySize,
                         GEMM_SMEM_BYTES);
    cudaFuncSetAttribute(gemm_tf32<1>,
                         cudaFuncAttributeMaxDynamicSharedMemorySize,
                         GEMM_SMEM_BYTES);
    cudaFuncSetAttribute(gemm_tf32<2>,
                         cudaFuncAttributeMaxDynamicSharedMemorySize,
                         GEMM_SMEM_BYTES);
    cudaFuncSetAttribute(attn_kernel,
                         cudaFuncAttributeMaxDynamicSharedMemorySize,
                         ATTN_SMEM_BYTES);

    gemm_tf32<0><<<dim3(2048 / 128, 8192 / 128), 256, GEMM_SMEM_BYTES>>>(enc, Wqk, bqk, nullptr, 1024, 2048);
    gemm_tf32<1><<<dim3(1024 / 128, 8192 / 128), 256, GEMM_SMEM_BYTES>>>(in_q, Wv, bv, nullptr, 1024, 1024);
    attn_kernel<<<dim3(16, 128), 128, ATTN_SMEM_BYTES>>>();
    gemm_tf32<2><<<dim3(1024 / 128, 8192 / 128), 256, GEMM_SMEM_BYTES>>>(nullptr, Wo, bo, out, 1024, 1024);
}